// round 14
// baseline (speedup 1.0000x reference)
#include <cuda_runtime.h>
#include <cuda_fp16.h>

// SpatialLoss: per-segment variance loss over batch 0 only.
// Round 14: R13's single fused kernel with the finalize race FIXED:
// __syncthreads() between the per-thread __threadfence() and the g_done
// increment (release), plus an acquire __threadfence() in the last block.

#define NSEG   2048
#define PIX    (1024 * 1024)
#define TPB    512
#define NBLK   148
#define TOTG   (PIX / 4)            // 262144 groups of 4 px
#define W      14                   // sorted slots per thread in P2
#define SLOTS  (TPB * W)            // 7168 >= max 7088 px/block

// smem byte offsets
#define ST_STAGE 0                  // uint4 [SLOTS]   114688
#define ST_SEGID 114688             // u16   [SLOTS]    14336
#define ST_POS   129024             // u16   [7088]     14336
#define ST_HIST  143360             // u32   [NSEG]      8192
#define ST_CURS  151552             // u32   [NSEG]      8192
#define ST_WSUM  159744             // u32   [16]          64
#define ST_WSUM2 159808             // u32   [16]          64
#define ST_LAST  159872             // u32   [1]
#define SMEM_BYTES 159936

__device__ __align__(16) __half2 g_sumh[NSEG * 32];  // [seg][32 half2] = 64 ch
__device__ float    g_ssq[NSEG];
__device__ float    g_cnt[NSEG];
__device__ unsigned g_done;

__device__ __forceinline__ void red8(__half2* p, __half2 a, __half2 b,
                                     __half2 c, __half2 d) {
    asm volatile("red.global.add.noftz.v4.f16x2 [%0], {%1,%2,%3,%4};"
                 :: "l"(p),
                    "r"(*(const unsigned*)&a), "r"(*(const unsigned*)&b),
                    "r"(*(const unsigned*)&c), "r"(*(const unsigned*)&d)
                 : "memory");
}
__device__ __forceinline__ void red1(float* p, float a) {
    asm volatile("red.global.add.f32 [%0], %1;" :: "l"(p), "f"(a) : "memory");
}
__device__ __forceinline__ uint4 ldcg16(const uint4* p) {
    uint4 v;
    asm volatile("ld.global.cg.v4.u32 {%0,%1,%2,%3}, [%4];"
                 : "=r"(v.x), "=r"(v.y), "=r"(v.z), "=r"(v.w) : "l"(p));
    return v;
}
__device__ __forceinline__ float ldcgf(const float* p) {
    float v;
    asm volatile("ld.global.cg.f32 %0, [%1];" : "=f"(v) : "l"(p));
    return v;
}

__global__ __launch_bounds__(TPB, 1)
void spatial_loss_kernel(const int* __restrict__ sp,
                         const float* __restrict__ feats,
                         float* __restrict__ out) {
    extern __shared__ char smem[];
    uint4*          stage = (uint4*)(smem + ST_STAGE);
    unsigned short* segid = (unsigned short*)(smem + ST_SEGID);
    unsigned short* pos   = (unsigned short*)(smem + ST_POS);
    unsigned*       hist  = (unsigned*)(smem + ST_HIST);
    unsigned*       curs  = (unsigned*)(smem + ST_CURS);
    unsigned*       wsum  = (unsigned*)(smem + ST_WSUM);
    unsigned*       slast = (unsigned*)(smem + ST_LAST);

    const int tid  = threadIdx.x;
    const int lane = tid & 31;
    const int wid  = tid >> 5;

    const int gstart = (int)(((long long)blockIdx.x       * TOTG) / NBLK);
    const int gend   = (int)(((long long)(blockIdx.x + 1) * TOTG) / NBLK);
    const int4* sp4  = (const int4*)sp;

    // init: hist = 0, segid = sentinel
    #pragma unroll
    for (int k = 0; k < 4; k++) hist[tid + k * TPB] = 0u;
    #pragma unroll
    for (int k = 0; k < W; k++) segid[tid + k * TPB] = 0xFFFFu;
    __syncthreads();

    // P0a: histogram of segment ids
    #pragma unroll
    for (int k = 0; k < 4; k++) {
        const int g = gstart + k * TPB + tid;
        if (g < gend) {
            const int4 s = sp4[g];
            atomicAdd(&hist[s.x], 1u); atomicAdd(&hist[s.y], 1u);
            atomicAdd(&hist[s.z], 1u); atomicAdd(&hist[s.w], 1u);
        }
    }
    __syncthreads();

    // P0b: exclusive scan (4 bins/thread, 16 warps)
    {
        unsigned h[4], tsum = 0u;
        #pragma unroll
        for (int j = 0; j < 4; j++) { h[j] = hist[4 * tid + j]; tsum += h[j]; }
        unsigned incl = tsum;
        #pragma unroll
        for (int d = 1; d < 32; d <<= 1) {
            const unsigned n = __shfl_up_sync(0xffffffffu, incl, d);
            if (lane >= d) incl += n;
        }
        if (lane == 31) wsum[wid] = incl;
        __syncthreads();
        if (wid == 0) {
            unsigned v = (lane < 16) ? wsum[lane] : 0u;
            #pragma unroll
            for (int d = 1; d < 16; d <<= 1) {
                const unsigned n = __shfl_up_sync(0xffffffffu, v, d);
                if (lane >= d) v += n;
            }
            if (lane < 16) wsum[lane] = v;
        }
        __syncthreads();
        const unsigned wexcl = (wid == 0) ? 0u : wsum[wid - 1];
        unsigned run = wexcl + incl - tsum;
        #pragma unroll
        for (int j = 0; j < 4; j++) { curs[4 * tid + j] = run; run += h[j]; }
    }
    __syncthreads();

    // P0c: scatter sorted positions + seg ids
    #pragma unroll
    for (int k = 0; k < 4; k++) {
        const int g = gstart + k * TPB + tid;
        if (g < gend) {
            const int4 s = sp4[g];
            const int lp = (g - gstart) * 4;
            unsigned p0 = atomicAdd(&curs[s.x], 1u);
            unsigned p1 = atomicAdd(&curs[s.y], 1u);
            unsigned p2 = atomicAdd(&curs[s.z], 1u);
            unsigned p3 = atomicAdd(&curs[s.w], 1u);
            pos[lp + 0] = (unsigned short)p0; segid[p0] = (unsigned short)s.x;
            pos[lp + 1] = (unsigned short)p1; segid[p1] = (unsigned short)s.y;
            pos[lp + 2] = (unsigned short)p2; segid[p2] = (unsigned short)s.z;
            pos[lp + 3] = (unsigned short)p3; segid[p3] = (unsigned short)s.w;
        }
    }
    __syncthreads();

    float q[4][4];
    #pragma unroll
    for (int k = 0; k < 4; k++) q[k][0] = q[k][1] = q[k][2] = q[k][3] = 0.f;

    for (int oct = 0; oct < 8; oct++) {
        // P1: load 8 channels, accumulate fp32 ssq, stage packed f16 sorted
        #pragma unroll
        for (int k = 0; k < 4; k++) {
            const int g = gstart + k * TPB + tid;
            if (g < gend) {
                const int p = g * 4;
                const float* f = feats + (size_t)(oct * 8) * PIX + p;
                const float4 v0 = *(const float4*)(f + 0 * (size_t)PIX);
                const float4 v1 = *(const float4*)(f + 1 * (size_t)PIX);
                const float4 v2 = *(const float4*)(f + 2 * (size_t)PIX);
                const float4 v3 = *(const float4*)(f + 3 * (size_t)PIX);
                const float4 v4 = *(const float4*)(f + 4 * (size_t)PIX);
                const float4 v5 = *(const float4*)(f + 5 * (size_t)PIX);
                const float4 v6 = *(const float4*)(f + 6 * (size_t)PIX);
                const float4 v7 = *(const float4*)(f + 7 * (size_t)PIX);

                q[k][0] += v0.x*v0.x + v1.x*v1.x + v2.x*v2.x + v3.x*v3.x
                         + v4.x*v4.x + v5.x*v5.x + v6.x*v6.x + v7.x*v7.x;
                q[k][1] += v0.y*v0.y + v1.y*v1.y + v2.y*v2.y + v3.y*v3.y
                         + v4.y*v4.y + v5.y*v5.y + v6.y*v6.y + v7.y*v7.y;
                q[k][2] += v0.z*v0.z + v1.z*v1.z + v2.z*v2.z + v3.z*v3.z
                         + v4.z*v4.z + v5.z*v5.z + v6.z*v6.z + v7.z*v7.z;
                q[k][3] += v0.w*v0.w + v1.w*v1.w + v2.w*v2.w + v3.w*v3.w
                         + v4.w*v4.w + v5.w*v5.w + v6.w*v6.w + v7.w*v7.w;

                const ushort4 ps = ((const ushort4*)pos)[g - gstart];
                uint4 t4; __half2 h;
                h = __floats2half2_rn(v0.x, v1.x); t4.x = *(unsigned*)&h;
                h = __floats2half2_rn(v2.x, v3.x); t4.y = *(unsigned*)&h;
                h = __floats2half2_rn(v4.x, v5.x); t4.z = *(unsigned*)&h;
                h = __floats2half2_rn(v6.x, v7.x); t4.w = *(unsigned*)&h;
                stage[ps.x] = t4;
                h = __floats2half2_rn(v0.y, v1.y); t4.x = *(unsigned*)&h;
                h = __floats2half2_rn(v2.y, v3.y); t4.y = *(unsigned*)&h;
                h = __floats2half2_rn(v4.y, v5.y); t4.z = *(unsigned*)&h;
                h = __floats2half2_rn(v6.y, v7.y); t4.w = *(unsigned*)&h;
                stage[ps.y] = t4;
                h = __floats2half2_rn(v0.z, v1.z); t4.x = *(unsigned*)&h;
                h = __floats2half2_rn(v2.z, v3.z); t4.y = *(unsigned*)&h;
                h = __floats2half2_rn(v4.z, v5.z); t4.z = *(unsigned*)&h;
                h = __floats2half2_rn(v6.z, v7.z); t4.w = *(unsigned*)&h;
                stage[ps.z] = t4;
                h = __floats2half2_rn(v0.w, v1.w); t4.x = *(unsigned*)&h;
                h = __floats2half2_rn(v2.w, v3.w); t4.y = *(unsigned*)&h;
                h = __floats2half2_rn(v4.w, v5.w); t4.z = *(unsigned*)&h;
                h = __floats2half2_rn(v6.w, v7.w); t4.w = *(unsigned*)&h;
                stage[ps.w] = t4;
            }
        }
        __syncthreads();

        // P2: divergence-free windowed run reduction over sorted stage
        {
            const int w0 = tid * W;
            unsigned cs = 0xFFFFu;
            __half2 a0 = __float2half2_rn(0.f), a1 = a0, a2 = a0, a3 = a0;
            #pragma unroll
            for (int i = 0; i < W; i++) {
                const unsigned sg = segid[w0 + i];
                if (sg != cs) {
                    if (cs != 0xFFFFu)
                        red8(&g_sumh[cs * 32 + oct * 4], a0, a1, a2, a3);
                    cs = sg;
                    a0 = a1 = a2 = a3 = __float2half2_rn(0.f);
                }
                if (sg != 0xFFFFu) {
                    const uint4 r = stage[w0 + i];
                    a0 = __hadd2(a0, *(const __half2*)&r.x);
                    a1 = __hadd2(a1, *(const __half2*)&r.y);
                    a2 = __hadd2(a2, *(const __half2*)&r.z);
                    a3 = __hadd2(a3, *(const __half2*)&r.w);
                }
            }
            if (cs != 0xFFFFu)
                red8(&g_sumh[cs * 32 + oct * 4], a0, a1, a2, a3);
        }
        __syncthreads();
    }

    // ssq flush (fp32 exact, 1 red1 per px)
    #pragma unroll
    for (int k = 0; k < 4; k++) {
        const int g = gstart + k * TPB + tid;
        if (g < gend) {
            const int4 s = sp4[g];
            red1(&g_ssq[s.x], q[k][0]);
            red1(&g_ssq[s.y], q[k][1]);
            red1(&g_ssq[s.z], q[k][2]);
            red1(&g_ssq[s.w], q[k][3]);
        }
    }

    // count flush (per present segment)
    #pragma unroll
    for (int k = 0; k < 4; k++) {
        const int seg = tid + k * TPB;
        const unsigned c = hist[seg];
        if (c) red1(&g_cnt[seg], (float)c);
    }

    // -------- finalize: last block reduces everything --------
    __threadfence();        // each thread: order its REDs to GPU scope
    __syncthreads();        // ALL threads' fences complete before counter bump
    if (tid == 0) {
        const unsigned old = atomicAdd(&g_done, 1u);
        *slast = (old == NBLK - 1) ? 1u : 0u;
    }
    __syncthreads();
    if (*slast == 0u) return;

    __threadfence();        // acquire: see all blocks' fenced REDs

    // last block: compute loss over 2048 segments (4 per thread)
    float loss = 0.0f, nz = 0.0f;
    #pragma unroll
    for (int k = 0; k < 4; k++) {
        const int seg = tid + k * TPB;
        float s2 = 0.0f;
        uint4* cell = (uint4*)&g_sumh[seg * 32];
        #pragma unroll
        for (int j = 0; j < 8; j++) {
            const uint4 raw = ldcg16(cell + j);
            const float2 e0 = __half22float2(*(const __half2*)&raw.x);
            const float2 e1 = __half22float2(*(const __half2*)&raw.y);
            const float2 e2 = __half22float2(*(const __half2*)&raw.z);
            const float2 e3 = __half22float2(*(const __half2*)&raw.w);
            s2 += e0.x * e0.x + e0.y * e0.y + e1.x * e1.x + e1.y * e1.y
                + e2.x * e2.x + e2.y * e2.y + e3.x * e3.x + e3.y * e3.y;
        }
        const uint4 z4 = make_uint4(0u, 0u, 0u, 0u);
        #pragma unroll
        for (int j = 0; j < 8; j++) cell[j] = z4;     // re-zero for replay

        const float n   = ldcgf(&g_cnt[seg]);
        const float ssq = ldcgf(&g_ssq[seg]);
        g_cnt[seg] = 0.0f; g_ssq[seg] = 0.0f;         // re-zero

        const float nn = fmaxf(n, 1.0f);
        const float per_seg = (ssq - s2 / nn) / (64.0f * nn);
        if (n >= 2.0f) loss += per_seg;
        if (n > 0.0f)  nz += 1.0f;
    }
    #pragma unroll
    for (int d = 16; d > 0; d >>= 1) {
        loss += __shfl_xor_sync(0xffffffffu, loss, d);
        nz   += __shfl_xor_sync(0xffffffffu, nz, d);
    }
    float* fl = (float*)(smem + ST_WSUM);    // 16 floats
    float* fn = (float*)(smem + ST_WSUM2);   // 16 floats
    if (lane == 0) { fl[wid] = loss; fn[wid] = nz; }
    __syncthreads();
    if (tid == 0) {
        float L = 0.f, N = 0.f;
        #pragma unroll
        for (int w = 0; w < 16; w++) { L += fl[w]; N += fn[w]; }
        out[0] = L / N;
        g_done = 0u;                   // reset for next replay
    }
}

extern "C" void kernel_launch(void* const* d_in, const int* in_sizes, int n_in,
                              void* d_out, int out_size) {
    const int* sp;
    const float* feats;
    if (in_sizes[0] == 2 * 1024 * 1024) {
        sp    = (const int*)d_in[0];
        feats = (const float*)d_in[1];
    } else {
        sp    = (const int*)d_in[1];
        feats = (const float*)d_in[0];
    }

    cudaFuncSetAttribute(spatial_loss_kernel,
                         cudaFuncAttributeMaxDynamicSharedMemorySize, SMEM_BYTES);

    spatial_loss_kernel<<<NBLK, TPB, SMEM_BYTES>>>(sp, feats, (float*)d_out);
}

// round 15
// speedup vs baseline: 1.0287x; 1.0287x over previous
#include <cuda_runtime.h>
#include <cuda_fp16.h>

// SpatialLoss: per-segment variance loss over batch 0 only.
// Round 15: occupancy fix. R14 profile showed occ=25%, all pipes <29% ->
// latency-bound. Now 296 blocks x 512 thr (3544 px/block), smem 86KB ->
// 2 CTAs/SM = 32 warps = 50% occ. Two-half P1 keeps regs under the
// __launch_bounds__(512,2) 64-reg cap (no spills).

#define NSEG   2048
#define PIX    (1024 * 1024)
#define TPB    512
#define NBLK   296
#define TOTG   (PIX / 4)            // 262144 groups of 4 px
#define W      7                    // sorted slots per thread in P2
#define SLOTS  (TPB * W)            // 3584 >= max 3544 px/block

// smem byte offsets
#define ST_STAGE 0                  // uint4 [SLOTS]    57344
#define ST_SEGID 57344              // u16   [SLOTS]     7168
#define ST_POS   64512              // u16   [3584]      7168
#define ST_HIST  71680              // u32   [NSEG]      8192
#define ST_CURS  79872              // u32   [NSEG]      8192
#define ST_WSUM  88064              // u32   [16]          64
#define ST_WSUM2 88128              // u32   [16]          64
#define ST_LAST  88192              // u32   [1]
#define SMEM_BYTES 88256

__device__ __align__(16) __half2 g_sumh[NSEG * 32];  // [seg][32 half2] = 64 ch
__device__ float    g_ssq[NSEG];
__device__ float    g_cnt[NSEG];
__device__ unsigned g_done;

__device__ __forceinline__ void red8(__half2* p, __half2 a, __half2 b,
                                     __half2 c, __half2 d) {
    asm volatile("red.global.add.noftz.v4.f16x2 [%0], {%1,%2,%3,%4};"
                 :: "l"(p),
                    "r"(*(const unsigned*)&a), "r"(*(const unsigned*)&b),
                    "r"(*(const unsigned*)&c), "r"(*(const unsigned*)&d)
                 : "memory");
}
__device__ __forceinline__ void red1(float* p, float a) {
    asm volatile("red.global.add.f32 [%0], %1;" :: "l"(p), "f"(a) : "memory");
}
__device__ __forceinline__ uint4 ldcg16(const uint4* p) {
    uint4 v;
    asm volatile("ld.global.cg.v4.u32 {%0,%1,%2,%3}, [%4];"
                 : "=r"(v.x), "=r"(v.y), "=r"(v.z), "=r"(v.w) : "l"(p));
    return v;
}
__device__ __forceinline__ float ldcgf(const float* p) {
    float v;
    asm volatile("ld.global.cg.f32 %0, [%1];" : "=f"(v) : "l"(p));
    return v;
}

__global__ __launch_bounds__(TPB, 2)
void spatial_loss_kernel(const int* __restrict__ sp,
                         const float* __restrict__ feats,
                         float* __restrict__ out) {
    extern __shared__ char smem[];
    uint4*          stage = (uint4*)(smem + ST_STAGE);
    unsigned short* segid = (unsigned short*)(smem + ST_SEGID);
    unsigned short* pos   = (unsigned short*)(smem + ST_POS);
    unsigned*       hist  = (unsigned*)(smem + ST_HIST);
    unsigned*       curs  = (unsigned*)(smem + ST_CURS);
    unsigned*       wsum  = (unsigned*)(smem + ST_WSUM);
    unsigned*       slast = (unsigned*)(smem + ST_LAST);

    const int tid  = threadIdx.x;
    const int lane = tid & 31;
    const int wid  = tid >> 5;

    const int gstart = (int)(((long long)blockIdx.x       * TOTG) / NBLK);
    const int gend   = (int)(((long long)(blockIdx.x + 1) * TOTG) / NBLK);
    const int4* sp4  = (const int4*)sp;

    // init: hist = 0, segid = sentinel
    #pragma unroll
    for (int k = 0; k < 4; k++) hist[tid + k * TPB] = 0u;
    #pragma unroll
    for (int k = 0; k < W; k++) segid[tid + k * TPB] = 0xFFFFu;
    __syncthreads();

    // P0a: histogram of segment ids
    #pragma unroll
    for (int k = 0; k < 2; k++) {
        const int g = gstart + k * TPB + tid;
        if (g < gend) {
            const int4 s = sp4[g];
            atomicAdd(&hist[s.x], 1u); atomicAdd(&hist[s.y], 1u);
            atomicAdd(&hist[s.z], 1u); atomicAdd(&hist[s.w], 1u);
        }
    }
    __syncthreads();

    // P0b: exclusive scan (4 bins/thread, 16 warps)
    {
        unsigned h[4], tsum = 0u;
        #pragma unroll
        for (int j = 0; j < 4; j++) { h[j] = hist[4 * tid + j]; tsum += h[j]; }
        unsigned incl = tsum;
        #pragma unroll
        for (int d = 1; d < 32; d <<= 1) {
            const unsigned n = __shfl_up_sync(0xffffffffu, incl, d);
            if (lane >= d) incl += n;
        }
        if (lane == 31) wsum[wid] = incl;
        __syncthreads();
        if (wid == 0) {
            unsigned v = (lane < 16) ? wsum[lane] : 0u;
            #pragma unroll
            for (int d = 1; d < 16; d <<= 1) {
                const unsigned n = __shfl_up_sync(0xffffffffu, v, d);
                if (lane >= d) v += n;
            }
            if (lane < 16) wsum[lane] = v;
        }
        __syncthreads();
        const unsigned wexcl = (wid == 0) ? 0u : wsum[wid - 1];
        unsigned run = wexcl + incl - tsum;
        #pragma unroll
        for (int j = 0; j < 4; j++) { curs[4 * tid + j] = run; run += h[j]; }
    }
    __syncthreads();

    // P0c: scatter sorted positions + seg ids
    #pragma unroll
    for (int k = 0; k < 2; k++) {
        const int g = gstart + k * TPB + tid;
        if (g < gend) {
            const int4 s = sp4[g];
            const int lp = (g - gstart) * 4;
            unsigned p0 = atomicAdd(&curs[s.x], 1u);
            unsigned p1 = atomicAdd(&curs[s.y], 1u);
            unsigned p2 = atomicAdd(&curs[s.z], 1u);
            unsigned p3 = atomicAdd(&curs[s.w], 1u);
            pos[lp + 0] = (unsigned short)p0; segid[p0] = (unsigned short)s.x;
            pos[lp + 1] = (unsigned short)p1; segid[p1] = (unsigned short)s.y;
            pos[lp + 2] = (unsigned short)p2; segid[p2] = (unsigned short)s.z;
            pos[lp + 3] = (unsigned short)p3; segid[p3] = (unsigned short)s.w;
        }
    }
    __syncthreads();

    float q[2][4];
    #pragma unroll
    for (int k = 0; k < 2; k++) q[k][0] = q[k][1] = q[k][2] = q[k][3] = 0.f;

    for (int oct = 0; oct < 8; oct++) {
        // P1: two 4-channel halves (register-lean), stage packed f16 sorted
        #pragma unroll
        for (int k = 0; k < 2; k++) {
            const int g = gstart + k * TPB + tid;
            if (g < gend) {
                const int p = g * 4;
                const float* f = feats + (size_t)(oct * 8) * PIX + p;

                // half 1: channels 0..3
                __half2 a0, a1, a2, a3, b0, b1, b2, b3;
                {
                    const float4 v0 = *(const float4*)(f + 0 * (size_t)PIX);
                    const float4 v1 = *(const float4*)(f + 1 * (size_t)PIX);
                    const float4 v2 = *(const float4*)(f + 2 * (size_t)PIX);
                    const float4 v3 = *(const float4*)(f + 3 * (size_t)PIX);
                    q[k][0] += v0.x*v0.x + v1.x*v1.x + v2.x*v2.x + v3.x*v3.x;
                    q[k][1] += v0.y*v0.y + v1.y*v1.y + v2.y*v2.y + v3.y*v3.y;
                    q[k][2] += v0.z*v0.z + v1.z*v1.z + v2.z*v2.z + v3.z*v3.z;
                    q[k][3] += v0.w*v0.w + v1.w*v1.w + v2.w*v2.w + v3.w*v3.w;
                    a0 = __floats2half2_rn(v0.x, v1.x); b0 = __floats2half2_rn(v2.x, v3.x);
                    a1 = __floats2half2_rn(v0.y, v1.y); b1 = __floats2half2_rn(v2.y, v3.y);
                    a2 = __floats2half2_rn(v0.z, v1.z); b2 = __floats2half2_rn(v2.z, v3.z);
                    a3 = __floats2half2_rn(v0.w, v1.w); b3 = __floats2half2_rn(v2.w, v3.w);
                }
                // half 2: channels 4..7 (reuse float4 regs)
                __half2 c0, c1, c2, c3, d0, d1, d2, d3;
                {
                    const float4 v0 = *(const float4*)(f + 4 * (size_t)PIX);
                    const float4 v1 = *(const float4*)(f + 5 * (size_t)PIX);
                    const float4 v2 = *(const float4*)(f + 6 * (size_t)PIX);
                    const float4 v3 = *(const float4*)(f + 7 * (size_t)PIX);
                    q[k][0] += v0.x*v0.x + v1.x*v1.x + v2.x*v2.x + v3.x*v3.x;
                    q[k][1] += v0.y*v0.y + v1.y*v1.y + v2.y*v2.y + v3.y*v3.y;
                    q[k][2] += v0.z*v0.z + v1.z*v1.z + v2.z*v2.z + v3.z*v3.z;
                    q[k][3] += v0.w*v0.w + v1.w*v1.w + v2.w*v2.w + v3.w*v3.w;
                    c0 = __floats2half2_rn(v0.x, v1.x); d0 = __floats2half2_rn(v2.x, v3.x);
                    c1 = __floats2half2_rn(v0.y, v1.y); d1 = __floats2half2_rn(v2.y, v3.y);
                    c2 = __floats2half2_rn(v0.z, v1.z); d2 = __floats2half2_rn(v2.z, v3.z);
                    c3 = __floats2half2_rn(v0.w, v1.w); d3 = __floats2half2_rn(v2.w, v3.w);
                }

                const ushort4 ps = ((const ushort4*)pos)[g - gstart];
                uint4 t4;
                t4.x = *(unsigned*)&a0; t4.y = *(unsigned*)&b0;
                t4.z = *(unsigned*)&c0; t4.w = *(unsigned*)&d0;
                stage[ps.x] = t4;
                t4.x = *(unsigned*)&a1; t4.y = *(unsigned*)&b1;
                t4.z = *(unsigned*)&c1; t4.w = *(unsigned*)&d1;
                stage[ps.y] = t4;
                t4.x = *(unsigned*)&a2; t4.y = *(unsigned*)&b2;
                t4.z = *(unsigned*)&c2; t4.w = *(unsigned*)&d2;
                stage[ps.z] = t4;
                t4.x = *(unsigned*)&a3; t4.y = *(unsigned*)&b3;
                t4.z = *(unsigned*)&c3; t4.w = *(unsigned*)&d3;
                stage[ps.w] = t4;
            }
        }
        __syncthreads();

        // P2: divergence-free windowed run reduction over sorted stage
        {
            const int w0 = tid * W;
            unsigned cs = 0xFFFFu;
            __half2 a0 = __float2half2_rn(0.f), a1 = a0, a2 = a0, a3 = a0;
            #pragma unroll
            for (int i = 0; i < W; i++) {
                const unsigned sg = segid[w0 + i];
                if (sg != cs) {
                    if (cs != 0xFFFFu)
                        red8(&g_sumh[cs * 32 + oct * 4], a0, a1, a2, a3);
                    cs = sg;
                    a0 = a1 = a2 = a3 = __float2half2_rn(0.f);
                }
                if (sg != 0xFFFFu) {
                    const uint4 r = stage[w0 + i];
                    a0 = __hadd2(a0, *(const __half2*)&r.x);
                    a1 = __hadd2(a1, *(const __half2*)&r.y);
                    a2 = __hadd2(a2, *(const __half2*)&r.z);
                    a3 = __hadd2(a3, *(const __half2*)&r.w);
                }
            }
            if (cs != 0xFFFFu)
                red8(&g_sumh[cs * 32 + oct * 4], a0, a1, a2, a3);
        }
        __syncthreads();
    }

    // ssq flush (fp32 exact, 1 red1 per px)
    #pragma unroll
    for (int k = 0; k < 2; k++) {
        const int g = gstart + k * TPB + tid;
        if (g < gend) {
            const int4 s = sp4[g];
            red1(&g_ssq[s.x], q[k][0]);
            red1(&g_ssq[s.y], q[k][1]);
            red1(&g_ssq[s.z], q[k][2]);
            red1(&g_ssq[s.w], q[k][3]);
        }
    }

    // count flush (per present segment)
    #pragma unroll
    for (int k = 0; k < 4; k++) {
        const int seg = tid + k * TPB;
        const unsigned c = hist[seg];
        if (c) red1(&g_cnt[seg], (float)c);
    }

    // -------- finalize: last block reduces everything --------
    __threadfence();        // each thread: order its REDs to GPU scope
    __syncthreads();        // all threads' fences before the counter bump
    if (tid == 0) {
        const unsigned old = atomicAdd(&g_done, 1u);
        *slast = (old == NBLK - 1) ? 1u : 0u;
    }
    __syncthreads();
    if (*slast == 0u) return;

    __threadfence();        // acquire side

    float loss = 0.0f, nz = 0.0f;
    #pragma unroll
    for (int k = 0; k < 4; k++) {
        const int seg = tid + k * TPB;
        float s2 = 0.0f;
        uint4* cell = (uint4*)&g_sumh[seg * 32];
        #pragma unroll
        for (int j = 0; j < 8; j++) {
            const uint4 raw = ldcg16(cell + j);
            const float2 e0 = __half22float2(*(const __half2*)&raw.x);
            const float2 e1 = __half22float2(*(const __half2*)&raw.y);
            const float2 e2 = __half22float2(*(const __half2*)&raw.z);
            const float2 e3 = __half22float2(*(const __half2*)&raw.w);
            s2 += e0.x * e0.x + e0.y * e0.y + e1.x * e1.x + e1.y * e1.y
                + e2.x * e2.x + e2.y * e2.y + e3.x * e3.x + e3.y * e3.y;
        }
        const uint4 z4 = make_uint4(0u, 0u, 0u, 0u);
        #pragma unroll
        for (int j = 0; j < 8; j++) cell[j] = z4;     // re-zero for replay

        const float n   = ldcgf(&g_cnt[seg]);
        const float ssq = ldcgf(&g_ssq[seg]);
        g_cnt[seg] = 0.0f; g_ssq[seg] = 0.0f;         // re-zero

        const float nn = fmaxf(n, 1.0f);
        const float per_seg = (ssq - s2 / nn) / (64.0f * nn);
        if (n >= 2.0f) loss += per_seg;
        if (n > 0.0f)  nz += 1.0f;
    }
    #pragma unroll
    for (int d = 16; d > 0; d >>= 1) {
        loss += __shfl_xor_sync(0xffffffffu, loss, d);
        nz   += __shfl_xor_sync(0xffffffffu, nz, d);
    }
    float* fl = (float*)(smem + ST_WSUM);
    float* fn = (float*)(smem + ST_WSUM2);
    if (lane == 0) { fl[wid] = loss; fn[wid] = nz; }
    __syncthreads();
    if (tid == 0) {
        float L = 0.f, N = 0.f;
        #pragma unroll
        for (int w = 0; w < 16; w++) { L += fl[w]; N += fn[w]; }
        out[0] = L / N;
        g_done = 0u;                   // reset for next replay
    }
}

extern "C" void kernel_launch(void* const* d_in, const int* in_sizes, int n_in,
                              void* d_out, int out_size) {
    const int* sp;
    const float* feats;
    if (in_sizes[0] == 2 * 1024 * 1024) {
        sp    = (const int*)d_in[0];
        feats = (const float*)d_in[1];
    } else {
        sp    = (const int*)d_in[1];
        feats = (const float*)d_in[0];
    }

    cudaFuncSetAttribute(spatial_loss_kernel,
                         cudaFuncAttributeMaxDynamicSharedMemorySize, SMEM_BYTES);

    spatial_loss_kernel<<<NBLK, TPB, SMEM_BYTES>>>(sp, feats, (float*)d_out);
}

// round 16
// speedup vs baseline: 1.2167x; 1.1827x over previous
#include <cuda_runtime.h>
#include <cuda_fp16.h>

// SpatialLoss: per-segment variance loss over batch 0 only.
// Round 16: low RED count AND high occupancy. 148 blocks x 1024 threads
// (7088 px/block -> run length 3.46 -> ~12M L2 atomic words) with one
// 32-warp CTA/SM = 50% occ. Split kernels (no fences; kernel boundary
// orders REDs). Two-half P1 keeps regs at the 64-reg cap without spills.

#define NSEG   2048
#define PIX    (1024 * 1024)
#define TPB    1024
#define NBLK   148
#define TOTG   (PIX / 4)            // 262144 groups of 4 px
#define W      7                    // sorted slots per thread in P2
#define SLOTS  (TPB * W)            // 7168 >= max 7088 px/block

// smem byte offsets
#define ST_STAGE 0                  // uint4 [SLOTS]   114688
#define ST_SEGID 114688             // u16   [SLOTS]    14336
#define ST_POS   129024             // u16   [7168]     14336
#define ST_HIST  143360             // u32   [NSEG]      8192
#define ST_CURS  151552             // u32   [NSEG]      8192
#define ST_WSUM  159744             // u32   [32]         128
#define SMEM_BYTES 159872

__device__ __align__(16) __half2 g_sumh[NSEG * 32];  // [seg][32 half2] = 64 ch
__device__ float    g_ssq[NSEG];
__device__ float    g_cnt[NSEG];
__device__ float    g_accx, g_accy;
__device__ unsigned g_done;

__device__ __forceinline__ void red8(__half2* p, __half2 a, __half2 b,
                                     __half2 c, __half2 d) {
    asm volatile("red.global.add.noftz.v4.f16x2 [%0], {%1,%2,%3,%4};"
                 :: "l"(p),
                    "r"(*(const unsigned*)&a), "r"(*(const unsigned*)&b),
                    "r"(*(const unsigned*)&c), "r"(*(const unsigned*)&d)
                 : "memory");
}
__device__ __forceinline__ void red1(float* p, float a) {
    asm volatile("red.global.add.f32 [%0], %1;" :: "l"(p), "f"(a) : "memory");
}

__global__ __launch_bounds__(TPB, 1)
void accum_kernel(const int* __restrict__ sp, const float* __restrict__ feats) {
    extern __shared__ char smem[];
    uint4*          stage = (uint4*)(smem + ST_STAGE);
    unsigned short* segid = (unsigned short*)(smem + ST_SEGID);
    unsigned short* pos   = (unsigned short*)(smem + ST_POS);
    unsigned*       hist  = (unsigned*)(smem + ST_HIST);
    unsigned*       curs  = (unsigned*)(smem + ST_CURS);
    unsigned*       wsum  = (unsigned*)(smem + ST_WSUM);

    const int tid  = threadIdx.x;
    const int lane = tid & 31;
    const int wid  = tid >> 5;

    const int gstart = (int)(((long long)blockIdx.x       * TOTG) / NBLK);
    const int gend   = (int)(((long long)(blockIdx.x + 1) * TOTG) / NBLK);
    const int4* sp4  = (const int4*)sp;

    // init: hist = 0, segid = sentinel
    hist[tid] = 0u; hist[tid + TPB] = 0u;
    #pragma unroll
    for (int k = 0; k < W; k++) segid[tid + k * TPB] = 0xFFFFu;
    __syncthreads();

    // P0a: histogram of segment ids
    #pragma unroll
    for (int k = 0; k < 2; k++) {
        const int g = gstart + k * TPB + tid;
        if (g < gend) {
            const int4 s = sp4[g];
            atomicAdd(&hist[s.x], 1u); atomicAdd(&hist[s.y], 1u);
            atomicAdd(&hist[s.z], 1u); atomicAdd(&hist[s.w], 1u);
        }
    }
    __syncthreads();

    // P0b: exclusive scan (2 bins/thread, 32 warps)
    {
        const unsigned h0 = hist[2 * tid], h1 = hist[2 * tid + 1];
        const unsigned tsum = h0 + h1;
        unsigned incl = tsum;
        #pragma unroll
        for (int d = 1; d < 32; d <<= 1) {
            const unsigned n = __shfl_up_sync(0xffffffffu, incl, d);
            if (lane >= d) incl += n;
        }
        if (lane == 31) wsum[wid] = incl;
        __syncthreads();
        if (wid == 0) {
            unsigned v = wsum[lane];
            #pragma unroll
            for (int d = 1; d < 32; d <<= 1) {
                const unsigned n = __shfl_up_sync(0xffffffffu, v, d);
                if (lane >= d) v += n;
            }
            wsum[lane] = v;
        }
        __syncthreads();
        const unsigned wexcl = (wid == 0) ? 0u : wsum[wid - 1];
        unsigned run = wexcl + incl - tsum;
        curs[2 * tid] = run; run += h0;
        curs[2 * tid + 1] = run;
    }
    __syncthreads();

    // P0c: scatter sorted positions + seg ids
    #pragma unroll
    for (int k = 0; k < 2; k++) {
        const int g = gstart + k * TPB + tid;
        if (g < gend) {
            const int4 s = sp4[g];
            const int lp = (g - gstart) * 4;
            unsigned p0 = atomicAdd(&curs[s.x], 1u);
            unsigned p1 = atomicAdd(&curs[s.y], 1u);
            unsigned p2 = atomicAdd(&curs[s.z], 1u);
            unsigned p3 = atomicAdd(&curs[s.w], 1u);
            pos[lp + 0] = (unsigned short)p0; segid[p0] = (unsigned short)s.x;
            pos[lp + 1] = (unsigned short)p1; segid[p1] = (unsigned short)s.y;
            pos[lp + 2] = (unsigned short)p2; segid[p2] = (unsigned short)s.z;
            pos[lp + 3] = (unsigned short)p3; segid[p3] = (unsigned short)s.w;
        }
    }
    __syncthreads();

    float q[2][4];
    #pragma unroll
    for (int k = 0; k < 2; k++) q[k][0] = q[k][1] = q[k][2] = q[k][3] = 0.f;

    for (int oct = 0; oct < 8; oct++) {
        // P1: two 4-channel halves (register-lean), stage packed f16 sorted
        #pragma unroll
        for (int k = 0; k < 2; k++) {
            const int g = gstart + k * TPB + tid;
            if (g < gend) {
                const int p = g * 4;
                const float* f = feats + (size_t)(oct * 8) * PIX + p;

                __half2 a0, a1, a2, a3, b0, b1, b2, b3;
                {
                    const float4 v0 = *(const float4*)(f + 0 * (size_t)PIX);
                    const float4 v1 = *(const float4*)(f + 1 * (size_t)PIX);
                    const float4 v2 = *(const float4*)(f + 2 * (size_t)PIX);
                    const float4 v3 = *(const float4*)(f + 3 * (size_t)PIX);
                    q[k][0] += v0.x*v0.x + v1.x*v1.x + v2.x*v2.x + v3.x*v3.x;
                    q[k][1] += v0.y*v0.y + v1.y*v1.y + v2.y*v2.y + v3.y*v3.y;
                    q[k][2] += v0.z*v0.z + v1.z*v1.z + v2.z*v2.z + v3.z*v3.z;
                    q[k][3] += v0.w*v0.w + v1.w*v1.w + v2.w*v2.w + v3.w*v3.w;
                    a0 = __floats2half2_rn(v0.x, v1.x); b0 = __floats2half2_rn(v2.x, v3.x);
                    a1 = __floats2half2_rn(v0.y, v1.y); b1 = __floats2half2_rn(v2.y, v3.y);
                    a2 = __floats2half2_rn(v0.z, v1.z); b2 = __floats2half2_rn(v2.z, v3.z);
                    a3 = __floats2half2_rn(v0.w, v1.w); b3 = __floats2half2_rn(v2.w, v3.w);
                }
                __half2 c0, c1, c2, c3, d0, d1, d2, d3;
                {
                    const float4 v0 = *(const float4*)(f + 4 * (size_t)PIX);
                    const float4 v1 = *(const float4*)(f + 5 * (size_t)PIX);
                    const float4 v2 = *(const float4*)(f + 6 * (size_t)PIX);
                    const float4 v3 = *(const float4*)(f + 7 * (size_t)PIX);
                    q[k][0] += v0.x*v0.x + v1.x*v1.x + v2.x*v2.x + v3.x*v3.x;
                    q[k][1] += v0.y*v0.y + v1.y*v1.y + v2.y*v2.y + v3.y*v3.y;
                    q[k][2] += v0.z*v0.z + v1.z*v1.z + v2.z*v2.z + v3.z*v3.z;
                    q[k][3] += v0.w*v0.w + v1.w*v1.w + v2.w*v2.w + v3.w*v3.w;
                    c0 = __floats2half2_rn(v0.x, v1.x); d0 = __floats2half2_rn(v2.x, v3.x);
                    c1 = __floats2half2_rn(v0.y, v1.y); d1 = __floats2half2_rn(v2.y, v3.y);
                    c2 = __floats2half2_rn(v0.z, v1.z); d2 = __floats2half2_rn(v2.z, v3.z);
                    c3 = __floats2half2_rn(v0.w, v1.w); d3 = __floats2half2_rn(v2.w, v3.w);
                }

                const ushort4 ps = ((const ushort4*)pos)[g - gstart];
                uint4 t4;
                t4.x = *(unsigned*)&a0; t4.y = *(unsigned*)&b0;
                t4.z = *(unsigned*)&c0; t4.w = *(unsigned*)&d0;
                stage[ps.x] = t4;
                t4.x = *(unsigned*)&a1; t4.y = *(unsigned*)&b1;
                t4.z = *(unsigned*)&c1; t4.w = *(unsigned*)&d1;
                stage[ps.y] = t4;
                t4.x = *(unsigned*)&a2; t4.y = *(unsigned*)&b2;
                t4.z = *(unsigned*)&c2; t4.w = *(unsigned*)&d2;
                stage[ps.z] = t4;
                t4.x = *(unsigned*)&a3; t4.y = *(unsigned*)&b3;
                t4.z = *(unsigned*)&c3; t4.w = *(unsigned*)&d3;
                stage[ps.w] = t4;
            }
        }
        __syncthreads();

        // P2: divergence-free windowed run reduction over sorted stage
        {
            const int w0 = tid * W;
            unsigned cs = 0xFFFFu;
            __half2 a0 = __float2half2_rn(0.f), a1 = a0, a2 = a0, a3 = a0;
            #pragma unroll
            for (int i = 0; i < W; i++) {
                const unsigned sg = segid[w0 + i];
                if (sg != cs) {
                    if (cs != 0xFFFFu)
                        red8(&g_sumh[cs * 32 + oct * 4], a0, a1, a2, a3);
                    cs = sg;
                    a0 = a1 = a2 = a3 = __float2half2_rn(0.f);
                }
                if (sg != 0xFFFFu) {
                    const uint4 r = stage[w0 + i];
                    a0 = __hadd2(a0, *(const __half2*)&r.x);
                    a1 = __hadd2(a1, *(const __half2*)&r.y);
                    a2 = __hadd2(a2, *(const __half2*)&r.z);
                    a3 = __hadd2(a3, *(const __half2*)&r.w);
                }
            }
            if (cs != 0xFFFFu)
                red8(&g_sumh[cs * 32 + oct * 4], a0, a1, a2, a3);
        }
        __syncthreads();
    }

    // ssq flush (fp32 exact, 1 red1 per px)
    #pragma unroll
    for (int k = 0; k < 2; k++) {
        const int g = gstart + k * TPB + tid;
        if (g < gend) {
            const int4 s = sp4[g];
            red1(&g_ssq[s.x], q[k][0]);
            red1(&g_ssq[s.y], q[k][1]);
            red1(&g_ssq[s.z], q[k][2]);
            red1(&g_ssq[s.w], q[k][3]);
        }
    }

    // count flush (per present segment)
    #pragma unroll
    for (int k = 0; k < 2; k++) {
        const int seg = tid + k * TPB;
        const unsigned c = hist[seg];
        if (c) red1(&g_cnt[seg], (float)c);
    }
}

__global__ void reduce_kernel(float* __restrict__ out) {
    __shared__ float sl[8], sn[8];
    const int seg = blockIdx.x * 256 + threadIdx.x;

    float s2 = 0.0f;
    uint4* cell = (uint4*)&g_sumh[seg * 32];
    #pragma unroll
    for (int j = 0; j < 8; j++) {
        const uint4 raw = cell[j];
        const float2 e0 = __half22float2(*(const __half2*)&raw.x);
        const float2 e1 = __half22float2(*(const __half2*)&raw.y);
        const float2 e2 = __half22float2(*(const __half2*)&raw.z);
        const float2 e3 = __half22float2(*(const __half2*)&raw.w);
        s2 += e0.x * e0.x + e0.y * e0.y + e1.x * e1.x + e1.y * e1.y
            + e2.x * e2.x + e2.y * e2.y + e3.x * e3.x + e3.y * e3.y;
    }
    const uint4 z4 = make_uint4(0u, 0u, 0u, 0u);
    #pragma unroll
    for (int j = 0; j < 8; j++) cell[j] = z4;   // re-zero for next replay

    const float n   = g_cnt[seg];
    const float ssq = g_ssq[seg];
    g_cnt[seg] = 0.0f; g_ssq[seg] = 0.0f;       // re-zero

    const float nn = fmaxf(n, 1.0f);
    const float per_seg = (ssq - s2 / nn) / (64.0f * nn);
    float loss = (n >= 2.0f) ? per_seg : 0.0f;
    float nz   = (n > 0.0f) ? 1.0f : 0.0f;
    #pragma unroll
    for (int d = 16; d > 0; d >>= 1) {
        loss += __shfl_xor_sync(0xffffffffu, loss, d);
        nz   += __shfl_xor_sync(0xffffffffu, nz, d);
    }
    const int lane = threadIdx.x & 31, wid = threadIdx.x >> 5;
    if (lane == 0) { sl[wid] = loss; sn[wid] = nz; }
    __syncthreads();
    if (threadIdx.x == 0) {
        float L = 0.f, N = 0.f;
        #pragma unroll
        for (int w = 0; w < 8; w++) { L += sl[w]; N += sn[w]; }
        atomicAdd(&g_accx, L);
        atomicAdd(&g_accy, N);
        __threadfence();
        const unsigned old = atomicAdd(&g_done, 1u);
        if (old == gridDim.x - 1) {
            const float lx = atomicAdd(&g_accx, 0.0f);
            const float ly = atomicAdd(&g_accy, 0.0f);
            out[0] = lx / ly;
            g_accx = 0.0f; g_accy = 0.0f; g_done = 0u;
        }
    }
}

extern "C" void kernel_launch(void* const* d_in, const int* in_sizes, int n_in,
                              void* d_out, int out_size) {
    const int* sp;
    const float* feats;
    if (in_sizes[0] == 2 * 1024 * 1024) {
        sp    = (const int*)d_in[0];
        feats = (const float*)d_in[1];
    } else {
        sp    = (const int*)d_in[1];
        feats = (const float*)d_in[0];
    }

    cudaFuncSetAttribute(accum_kernel,
                         cudaFuncAttributeMaxDynamicSharedMemorySize, SMEM_BYTES);

    accum_kernel<<<NBLK, TPB, SMEM_BYTES>>>(sp, feats);
    reduce_kernel<<<NSEG / 256, 256>>>((float*)d_out);
}